// round 11
// baseline (speedup 1.0000x reference)
#include <cuda_runtime.h>

#define BATCH 8
#define HH 1024
#define WW 1024

#define TILE 104          // valid output span per tile dim
#define HALO 12           // >= 10 needed; 12 keeps float4 alignment
#define EXT  128          // TILE + 2*HALO
#define NWARP 16
#define RPW  8            // rows per warp (NWARP*RPW == EXT)
#define NT   512
#define NITER 10

#define SMEM_BYTES ((2*EXT*EXT + 2*NWARP*EXT) * 4)

// sigmoid(2x) = 0.5*tanh(x) + 0.5  -> one MUFU
__device__ __forceinline__ float tanh_fast(float x) {
    float y;
    asm("tanh.approx.f32 %0, %1;" : "=f"(y) : "f"(x));
    return y;
}

// smem fields hold h = -0.5 * vf (masked to zero outside the image).
// q-step:  q  = max(q + (u_dn - u)*h1 + (u_rt - u)*h0, 0)
// u-step:  s  = h1*q + h0*q - h1p*qp - (h0*q)_left ;  x = o + 2*s  ( = o - Tq )
template <bool INTERIOR>
__device__ __forceinline__ void run_tile(
    const float* __restrict__ o, const float* __restrict__ vf,
    float* __restrict__ out, float* sm, int tx, int ty, int b)
{
    float* sh0 = sm;                    // h0 = -0.5*vf0 [EXT][EXT]
    float* sh1 = sm + EXT * EXT;        // h1 = -0.5*vf1 [EXT][EXT]
    float* xu  = sm + 2 * EXT * EXT;    // per-warp u row-0 exchange [NWARP][EXT]
    float* xq  = xu + NWARP * EXT;      // per-warp q row-7 exchange [NWARP][EXT]

    const int tid  = threadIdx.x;
    const int w    = tid >> 5;
    const int lane = tid & 31;
    const int gi0 = ty * TILE - HALO;
    const int gj0 = tx * TILE - HALO;            // multiple of 4
    const int colbase = gj0 + lane * 4;          // global col of this lane's elem 0
    const int cb = INTERIOR ? colbase : min(max(colbase, 0), WW - 4); // 16B aligned
    const int er0 = w * RPW;
    const float* ob = o + (size_t)b * HH * WW;

    // column in-image mask (boundary tiles only)
    float cmx, cmy, cmz, cmw;
    if (!INTERIOR) {
        cmx = ((unsigned)(colbase + 0) < WW) ? 1.f : 0.f;
        cmy = ((unsigned)(colbase + 1) < WW) ? 1.f : 0.f;
        cmz = ((unsigned)(colbase + 2) < WW) ? 1.f : 0.f;
        cmw = ((unsigned)(colbase + 3) < WW) ? 1.f : 0.f;
    }

    // ---- load vector field into smem as h = -0.5*vf, deinterleaved, masked ----
    for (int k = tid; k < EXT * EXT / 2; k += NT) {
        int er = k >> 6;              // 64 px-pairs per 128-col row
        int ec = (k & 63) << 1;
        int gr = gi0 + er;
        int gc = gj0 + ec;
        if (INTERIOR) {
            float4 v = *reinterpret_cast<const float4*>(vf + ((size_t)gr * WW + gc) * 2);
            sh0[er * EXT + ec]     = -0.5f * v.x;  sh1[er * EXT + ec]     = -0.5f * v.y;
            sh0[er * EXT + ec + 1] = -0.5f * v.z;  sh1[er * EXT + ec + 1] = -0.5f * v.w;
        } else {
            int grc = min(max(gr, 0), HH - 1);
            int gcc = min(max(gc, 0), WW - 2);
            float4 v = *reinterpret_cast<const float4*>(vf + ((size_t)grc * WW + gcc) * 2);
            float mr = ((unsigned)gr < HH) ? -0.5f : 0.f;
            float m0 = mr * (((unsigned)gc < WW) ? 1.f : 0.f);
            float m1 = mr * (((unsigned)(gc + 1) < WW) ? 1.f : 0.f);
            sh0[er * EXT + ec]     = v.x * m0;  sh1[er * EXT + ec]     = v.y * m0;
            sh0[er * EXT + ec + 1] = v.z * m1;  sh1[er * EXT + ec + 1] = v.w * m1;
        }
    }

    // ---- init: u = 0.5*tanh(o)+0.5 (masked on boundary), q = 0 ----
    float4 u[RPW], q[RPW];
#pragma unroll
    for (int r = 0; r < RPW; r++) {
        int er = er0 + r;
        int gr = gi0 + er;
        int grc = INTERIOR ? gr : min(max(gr, 0), HH - 1);
        float4 o4 = *reinterpret_cast<const float4*>(ob + (size_t)grc * WW + cb);
        if (INTERIOR) {
            u[r].x = fmaf(tanh_fast(o4.x), 0.5f, 0.5f);
            u[r].y = fmaf(tanh_fast(o4.y), 0.5f, 0.5f);
            u[r].z = fmaf(tanh_fast(o4.z), 0.5f, 0.5f);
            u[r].w = fmaf(tanh_fast(o4.w), 0.5f, 0.5f);
        } else {
            float rm = ((unsigned)gr < HH) ? 1.f : 0.f;
            u[r].x = (cmx * rm) * fmaf(tanh_fast(o4.x), 0.5f, 0.5f);
            u[r].y = (cmy * rm) * fmaf(tanh_fast(o4.y), 0.5f, 0.5f);
            u[r].z = (cmz * rm) * fmaf(tanh_fast(o4.z), 0.5f, 0.5f);
            u[r].w = (cmw * rm) * fmaf(tanh_fast(o4.w), 0.5f, 0.5f);
        }
        q[r] = make_float4(0.f, 0.f, 0.f, 0.f);
    }
    *reinterpret_cast<float4*>(&xu[w * EXT + lane * 4]) = u[0];
    __syncthreads();

#pragma unroll 1
    for (int it = 0; it < NITER; it++) {
        const bool last = (it == NITER - 1);

        // ===== fused sweep: per row r: q_new[r]; then (r>=1) u_new[r] =====
        {
            // prefetches: row er0 field vectors + the r=RPW-1 down-neighbor u
            float4 H0n = *reinterpret_cast<float4*>(&sh0[er0 * EXT + lane * 4]);
            float4 H1n = *reinterpret_cast<float4*>(&sh1[er0 * EXT + lane * 4]);
            float4 udl;
            if (w < NWARP - 1) udl = *reinterpret_cast<float4*>(&xu[(w + 1) * EXT + lane * 4]);
            else               udl = make_float4(0.f, 0.f, 0.f, 0.f);
            float4 h1prev;
#pragma unroll
            for (int r = 0; r < RPW; r++) {
                int er = er0 + r;
                float4 H0c = H0n, H1c = H1n;
                if (r < RPW - 1) {
                    H0n = *reinterpret_cast<float4*>(&sh0[(er + 1) * EXT + lane * 4]);
                    H1n = *reinterpret_cast<float4*>(&sh1[(er + 1) * EXT + lane * 4]);
                }
                // early o load for this row's u-step (L1 hit, overlaps math)
                int gr = gi0 + er;
                int grc = INTERIOR ? gr : min(max(gr, 0), HH - 1);
                float4 o4;
                if (r >= 1) o4 = *reinterpret_cast<const float4*>(ob + (size_t)grc * WW + cb);

                // ---- q-update row r (prev-iter u) ----
                float4 ud = (r < RPW - 1) ? u[r + 1] : udl;
                float ur = __shfl_down_sync(0xffffffffu, u[r].x, 1);
                if (lane == 31) ur = 0.f;
                q[r].x = fmaxf(fmaf(ud.x - u[r].x, H1c.x, fmaf(u[r].y - u[r].x, H0c.x, q[r].x)), 0.f);
                q[r].y = fmaxf(fmaf(ud.y - u[r].y, H1c.y, fmaf(u[r].z - u[r].y, H0c.y, q[r].y)), 0.f);
                q[r].z = fmaxf(fmaf(ud.z - u[r].z, H1c.z, fmaf(u[r].w - u[r].z, H0c.z, q[r].z)), 0.f);
                q[r].w = fmaxf(fmaf(ud.w - u[r].w, H1c.w, fmaf(ur     - u[r].w, H0c.w, q[r].w)), 0.f);

                // ---- u-update row r (r>=1) ----
                if (r >= 1) {
                    float4 sp;
                    sp.x = H0c.x * q[r].x;
                    sp.y = H0c.y * q[r].y;
                    sp.z = H0c.z * q[r].z;
                    sp.w = H0c.w * q[r].w;
                    float spl = __shfl_up_sync(0xffffffffu, sp.w, 1);
                    if (lane == 0) spl = 0.f;

                    float s0 = fmaf(H1c.x, q[r].x, sp.x);
                    s0 = fmaf(-h1prev.x, q[r-1].x, s0) - spl;
                    float s1 = fmaf(H1c.y, q[r].y, sp.y);
                    s1 = fmaf(-h1prev.y, q[r-1].y, s1) - sp.x;
                    float s2 = fmaf(H1c.z, q[r].z, sp.z);
                    s2 = fmaf(-h1prev.z, q[r-1].z, s2) - sp.y;
                    float s3 = fmaf(H1c.w, q[r].w, sp.w);
                    s3 = fmaf(-h1prev.w, q[r-1].w, s3) - sp.z;
                    float x0 = fmaf(2.f, s0, o4.x);
                    float x1 = fmaf(2.f, s1, o4.y);
                    float x2 = fmaf(2.f, s2, o4.z);
                    float x3 = fmaf(2.f, s3, o4.w);

                    if (!last) {
                        if (INTERIOR) {
                            u[r].x = fmaf(tanh_fast(x0), 0.5f, 0.5f);
                            u[r].y = fmaf(tanh_fast(x1), 0.5f, 0.5f);
                            u[r].z = fmaf(tanh_fast(x2), 0.5f, 0.5f);
                            u[r].w = fmaf(tanh_fast(x3), 0.5f, 0.5f);
                        } else {
                            float rm = ((unsigned)gr < HH) ? 1.f : 0.f;
                            u[r].x = (cmx * rm) * fmaf(tanh_fast(x0), 0.5f, 0.5f);
                            u[r].y = (cmy * rm) * fmaf(tanh_fast(x1), 0.5f, 0.5f);
                            u[r].z = (cmz * rm) * fmaf(tanh_fast(x2), 0.5f, 0.5f);
                            u[r].w = (cmw * rm) * fmaf(tanh_fast(x3), 0.5f, 0.5f);
                        }
                    } else {
                        bool ok = (er >= HALO && er < HALO + TILE &&
                                   lane >= HALO / 4 && lane < (HALO + TILE) / 4);
                        if (!INTERIOR) ok = ok && gr < HH && colbase < WW;
                        if (ok) {
                            *reinterpret_cast<float4*>(out + (size_t)((b * HH + gr) * WW + colbase)) =
                                make_float4(2.f * x0, 2.f * x1, 2.f * x2, 2.f * x3);
                        }
                    }
                }
                h1prev = H1c;
            }
        }
        *reinterpret_cast<float4*>(&xq[w * EXT + lane * 4]) = q[RPW - 1];
        __syncthreads();

        // ===== epilogue: u-update row 0 (needs q[7] of warp above) =====
        {
            int er = er0;
            int gr = gi0 + er;
            int grc = INTERIOR ? gr : min(max(gr, 0), HH - 1);
            float4 qup, h1p;
            if (w > 0) {
                qup = *reinterpret_cast<float4*>(&xq[(w - 1) * EXT + lane * 4]);
                h1p = *reinterpret_cast<float4*>(&sh1[(er0 - 1) * EXT + lane * 4]);
            } else {
                qup = make_float4(0.f, 0.f, 0.f, 0.f);
                h1p = make_float4(0.f, 0.f, 0.f, 0.f);
            }
            float4 H00 = *reinterpret_cast<float4*>(&sh0[er * EXT + lane * 4]);
            float4 H10 = *reinterpret_cast<float4*>(&sh1[er * EXT + lane * 4]);
            float4 o4 = *reinterpret_cast<const float4*>(ob + (size_t)grc * WW + cb);

            float4 sp;
            sp.x = H00.x * q[0].x;
            sp.y = H00.y * q[0].y;
            sp.z = H00.z * q[0].z;
            sp.w = H00.w * q[0].w;
            float spl = __shfl_up_sync(0xffffffffu, sp.w, 1);
            if (lane == 0) spl = 0.f;

            float s0 = fmaf(H10.x, q[0].x, sp.x);
            s0 = fmaf(-h1p.x, qup.x, s0) - spl;
            float s1 = fmaf(H10.y, q[0].y, sp.y);
            s1 = fmaf(-h1p.y, qup.y, s1) - sp.x;
            float s2 = fmaf(H10.z, q[0].z, sp.z);
            s2 = fmaf(-h1p.z, qup.z, s2) - sp.y;
            float s3 = fmaf(H10.w, q[0].w, sp.w);
            s3 = fmaf(-h1p.w, qup.w, s3) - sp.z;
            float x0 = fmaf(2.f, s0, o4.x);
            float x1 = fmaf(2.f, s1, o4.y);
            float x2 = fmaf(2.f, s2, o4.z);
            float x3 = fmaf(2.f, s3, o4.w);

            if (!last) {
                if (INTERIOR) {
                    u[0].x = fmaf(tanh_fast(x0), 0.5f, 0.5f);
                    u[0].y = fmaf(tanh_fast(x1), 0.5f, 0.5f);
                    u[0].z = fmaf(tanh_fast(x2), 0.5f, 0.5f);
                    u[0].w = fmaf(tanh_fast(x3), 0.5f, 0.5f);
                } else {
                    float rm = ((unsigned)gr < HH) ? 1.f : 0.f;
                    u[0].x = (cmx * rm) * fmaf(tanh_fast(x0), 0.5f, 0.5f);
                    u[0].y = (cmy * rm) * fmaf(tanh_fast(x1), 0.5f, 0.5f);
                    u[0].z = (cmz * rm) * fmaf(tanh_fast(x2), 0.5f, 0.5f);
                    u[0].w = (cmw * rm) * fmaf(tanh_fast(x3), 0.5f, 0.5f);
                }
                *reinterpret_cast<float4*>(&xu[w * EXT + lane * 4]) = u[0];
            } else {
                bool ok = (er >= HALO && er < HALO + TILE &&
                           lane >= HALO / 4 && lane < (HALO + TILE) / 4);
                if (!INTERIOR) ok = ok && gr < HH && colbase < WW;
                if (ok) {
                    *reinterpret_cast<float4*>(out + (size_t)((b * HH + gr) * WW + colbase)) =
                        make_float4(2.f * x0, 2.f * x1, 2.f * x2, 2.f * x3);
                }
            }
        }
        if (!last) __syncthreads();
    }
}

__global__ void __launch_bounds__(NT, 1)
ccs_fused(const float* __restrict__ o, const float* __restrict__ vf,
          float* __restrict__ out) {
    extern __shared__ float sm[];
    const int tx = blockIdx.x, ty = blockIdx.y, b = blockIdx.z;
    // interior tile: its EXT window never leaves the image
    const bool interior = (tx >= 1) && (tx <= 8) && (ty >= 1) && (ty <= 8);
    if (interior) run_tile<true >(o, vf, out, sm, tx, ty, b);
    else          run_tile<false>(o, vf, out, sm, tx, ty, b);
}

extern "C" void kernel_launch(void* const* d_in, const int* in_sizes, int n_in,
                              void* d_out, int out_size) {
    const float* o  = (const float*)d_in[0];
    const float* vf = (const float*)d_in[1];
    float* out = (float*)d_out;

    static bool attr_set = false;
    if (!attr_set) {
        cudaFuncSetAttribute(ccs_fused, cudaFuncAttributeMaxDynamicSharedMemorySize,
                             SMEM_BYTES);
        attr_set = true;
    }

    dim3 grid((WW + TILE - 1) / TILE, (HH + TILE - 1) / TILE, BATCH);  // 10 x 10 x 8
    ccs_fused<<<grid, NT, SMEM_BYTES>>>(o, vf, out);
}